// round 2
// baseline (speedup 1.0000x reference)
#include <cuda_runtime.h>
#include <math_constants.h>

// N = 4096 mention-ranking loss, collapsed to one streaming pass:
//   bestM_i = max over masked entries of row i (tril from ana_scores, diag from eps)
//   maxU_i  = max over unmasked strict-lower entries
//   loss_i = max(0, row_cost*(1+maxU-bestM), (1-mask_ii)*fnc*(1+eps-bestM))
// Mask rows are 16B-aligned -> LDG.128. ana rows unaligned -> scalar LDG.32 x4.

#define NMENT 4096
#define BLOCK 256

__device__ __forceinline__ void acc_one(float m, float s, float& bestM, float& maxU)
{
    if (m > 0.5f) bestM = fmaxf(bestM, s);
    else          maxU  = fmaxf(maxU,  s);
}

__global__ __launch_bounds__(BLOCK)
void mention_loss_kernel(const float* __restrict__ eps_scores,
                         const float* __restrict__ ana_scores,
                         const float* __restrict__ mask,
                         const float* __restrict__ link_costs,
                         const float* __restrict__ false_new_cost,
                         float* __restrict__ out)
{
    // Longest rows first: self-balancing tail (shortest rows fill last slots).
    const int row = NMENT - 1 - (int)blockIdx.x;
    const int tid = (int)threadIdx.x;

    const float* __restrict__ mrow = mask + (size_t)row * NMENT;   // 16B-aligned
    const long long abase = ((long long)row * (row - 1)) >> 1;
    const float* __restrict__ arow = ana_scores + abase;           // arbitrary align

    float bestM = -CUDART_INF_F;
    float maxU  = -CUDART_INF_F;

    const int nvec = row >> 2;                 // # of full float4 groups in [0,row)
    const float4* __restrict__ mrow4 = (const float4*)mrow;

    // Main vector loop, 2 groups (8 elements) per thread per iteration.
    int v = tid;
    for (; v + BLOCK < nvec; v += 2 * BLOCK) {
        const float4 m0 = __ldg(mrow4 + v);
        const float4 m1 = __ldg(mrow4 + v + BLOCK);
        const int j0 = v << 2;
        const int j1 = (v + BLOCK) << 2;
        const float s00 = __ldg(arow + j0 + 0);
        const float s01 = __ldg(arow + j0 + 1);
        const float s02 = __ldg(arow + j0 + 2);
        const float s03 = __ldg(arow + j0 + 3);
        const float s10 = __ldg(arow + j1 + 0);
        const float s11 = __ldg(arow + j1 + 1);
        const float s12 = __ldg(arow + j1 + 2);
        const float s13 = __ldg(arow + j1 + 3);
        acc_one(m0.x, s00, bestM, maxU);
        acc_one(m0.y, s01, bestM, maxU);
        acc_one(m0.z, s02, bestM, maxU);
        acc_one(m0.w, s03, bestM, maxU);
        acc_one(m1.x, s10, bestM, maxU);
        acc_one(m1.y, s11, bestM, maxU);
        acc_one(m1.z, s12, bestM, maxU);
        acc_one(m1.w, s13, bestM, maxU);
    }
    for (; v < nvec; v += BLOCK) {
        const float4 m0 = __ldg(mrow4 + v);
        const int j0 = v << 2;
        const float s0 = __ldg(arow + j0 + 0);
        const float s1 = __ldg(arow + j0 + 1);
        const float s2 = __ldg(arow + j0 + 2);
        const float s3 = __ldg(arow + j0 + 3);
        acc_one(m0.x, s0, bestM, maxU);
        acc_one(m0.y, s1, bestM, maxU);
        acc_one(m0.z, s2, bestM, maxU);
        acc_one(m0.w, s3, bestM, maxU);
    }
    // Scalar tail: j in [nvec*4, row)
    for (int j = (nvec << 2) + tid; j < row; j += BLOCK) {
        acc_one(__ldg(mrow + j), __ldg(arow + j), bestM, maxU);
    }

    // Block reduction of (bestM, maxU)
    __shared__ float sM[BLOCK / 32];
    __shared__ float sU[BLOCK / 32];

    #pragma unroll
    for (int off = 16; off > 0; off >>= 1) {
        bestM = fmaxf(bestM, __shfl_xor_sync(0xffffffffu, bestM, off));
        maxU  = fmaxf(maxU,  __shfl_xor_sync(0xffffffffu, maxU,  off));
    }
    const int warp = tid >> 5;
    const int lane = tid & 31;
    if (lane == 0) { sM[warp] = bestM; sU[warp] = maxU; }
    __syncthreads();

    if (warp == 0) {
        bestM = (lane < BLOCK / 32) ? sM[lane] : -CUDART_INF_F;
        maxU  = (lane < BLOCK / 32) ? sU[lane] : -CUDART_INF_F;
        #pragma unroll
        for (int off = 4; off > 0; off >>= 1) {
            bestM = fmaxf(bestM, __shfl_xor_sync(0xffffffffu, bestM, off));
            maxU  = fmaxf(maxU,  __shfl_xor_sync(0xffffffffu, maxU,  off));
        }
        if (lane == 0) {
            const float nonana = __ldg(mrow + row);     // mask diagonal
            const float e      = __ldg(eps_scores + row);
            if (nonana > 0.5f) bestM = fmaxf(bestM, e);

            const float lc0 = __ldg(link_costs + 0);    // false_link
            const float lc1 = __ldg(link_costs + 1);    // wrong_link
            const float fnc = __ldg(false_new_cost);

            const float row_cost = nonana * lc0 + (1.0f - nonana) * lc1;

            float loss = 0.0f;
            loss = fmaxf(loss, row_cost * (1.0f + maxU - bestM));   // -inf-safe
            const float dcost = (1.0f - nonana) * fnc;
            loss = fmaxf(loss, dcost * (1.0f + e - bestM));

            out[row] = loss;
        }
    }
}

extern "C" void kernel_launch(void* const* d_in, const int* in_sizes, int n_in,
                              void* d_out, int out_size)
{
    const float* eps  = (const float*)d_in[0];
    const float* ana  = (const float*)d_in[1];
    const float* mask = (const float*)d_in[2];
    const float* lc   = (const float*)d_in[3];
    const float* fnc  = (const float*)d_in[4];
    float* out = (float*)d_out;

    mention_loss_kernel<<<NMENT, BLOCK>>>(eps, ana, mask, lc, fnc, out);
}

// round 3
// speedup vs baseline: 1.1604x; 1.1604x over previous
#include <cuda_runtime.h>
#include <math_constants.h>

// N = 4096 mention-ranking loss, one streaming pass, row-PAIRED for balance:
// CTA b handles rows {b, 4095-b} -> exactly ~4095 elements per CTA (uniform).
// 2048 CTAs x 128 threads, 14 CTAs/SM -> whole grid is ONE resident wave.

#define NMENT 4096
#define BLOCK 128

__device__ __forceinline__ void acc_one(float m, float s, float& bestM, float& maxU)
{
    if (m > 0.5f) bestM = fmaxf(bestM, s);
    else          maxU  = fmaxf(maxU,  s);
}

__global__ __launch_bounds__(BLOCK, 14)
void mention_loss_kernel(const float* __restrict__ eps_scores,
                         const float* __restrict__ ana_scores,
                         const float* __restrict__ mask,
                         const float* __restrict__ link_costs,
                         const float* __restrict__ false_new_cost,
                         float* __restrict__ out)
{
    const int b   = (int)blockIdx.x;        // 0..2047
    const int tid = (int)threadIdx.x;
    const int warp = tid >> 5;
    const int lane = tid & 31;

    __shared__ float sM[2][BLOCK / 32];
    __shared__ float sU[2][BLOCK / 32];

    const float lc0 = __ldg(link_costs + 0);    // false_link
    const float lc1 = __ldg(link_costs + 1);    // wrong_link
    const float fnc = __ldg(false_new_cost);

    #pragma unroll
    for (int r = 0; r < 2; ++r) {
        const int row = (r == 0) ? b : (NMENT - 1 - b);

        const float* __restrict__ mrow = mask + (size_t)row * NMENT;   // 16B-aligned
        const long long abase = ((long long)row * (row - 1)) >> 1;
        const float* __restrict__ arow = ana_scores + abase;           // arbitrary align

        float bestM = -CUDART_INF_F;
        float maxU  = -CUDART_INF_F;

        const int nvec = row >> 2;             // full float4 groups in [0,row)
        const float4* __restrict__ mrow4 = (const float4*)mrow;

        int v = tid;
        for (; v + BLOCK < nvec; v += 2 * BLOCK) {
            const float4 m0 = __ldg(mrow4 + v);
            const float4 m1 = __ldg(mrow4 + v + BLOCK);
            const int j0 = v << 2;
            const int j1 = (v + BLOCK) << 2;
            const float s00 = __ldg(arow + j0 + 0);
            const float s01 = __ldg(arow + j0 + 1);
            const float s02 = __ldg(arow + j0 + 2);
            const float s03 = __ldg(arow + j0 + 3);
            const float s10 = __ldg(arow + j1 + 0);
            const float s11 = __ldg(arow + j1 + 1);
            const float s12 = __ldg(arow + j1 + 2);
            const float s13 = __ldg(arow + j1 + 3);
            acc_one(m0.x, s00, bestM, maxU);
            acc_one(m0.y, s01, bestM, maxU);
            acc_one(m0.z, s02, bestM, maxU);
            acc_one(m0.w, s03, bestM, maxU);
            acc_one(m1.x, s10, bestM, maxU);
            acc_one(m1.y, s11, bestM, maxU);
            acc_one(m1.z, s12, bestM, maxU);
            acc_one(m1.w, s13, bestM, maxU);
        }
        for (; v < nvec; v += BLOCK) {
            const float4 m0 = __ldg(mrow4 + v);
            const int j0 = v << 2;
            const float s0 = __ldg(arow + j0 + 0);
            const float s1 = __ldg(arow + j0 + 1);
            const float s2 = __ldg(arow + j0 + 2);
            const float s3 = __ldg(arow + j0 + 3);
            acc_one(m0.x, s0, bestM, maxU);
            acc_one(m0.y, s1, bestM, maxU);
            acc_one(m0.z, s2, bestM, maxU);
            acc_one(m0.w, s3, bestM, maxU);
        }
        for (int j = (nvec << 2) + tid; j < row; j += BLOCK) {
            acc_one(__ldg(mrow + j), __ldg(arow + j), bestM, maxU);
        }

        // Warp reduction
        #pragma unroll
        for (int off = 16; off > 0; off >>= 1) {
            bestM = fmaxf(bestM, __shfl_xor_sync(0xffffffffu, bestM, off));
            maxU  = fmaxf(maxU,  __shfl_xor_sync(0xffffffffu, maxU,  off));
        }
        if (lane == 0) { sM[r][warp] = bestM; sU[r][warp] = maxU; }
    }

    __syncthreads();

    // One warp finalizes both rows (4 partials each).
    if (warp == 0 && lane < 2) {
        const int r = lane;
        const int row = (r == 0) ? b : (NMENT - 1 - b);

        float bestM = fmaxf(fmaxf(sM[r][0], sM[r][1]), fmaxf(sM[r][2], sM[r][3]));
        float maxU  = fmaxf(fmaxf(sU[r][0], sU[r][1]), fmaxf(sU[r][2], sU[r][3]));

        const float* __restrict__ mrow = mask + (size_t)row * NMENT;
        const float nonana = __ldg(mrow + row);     // mask diagonal
        const float e      = __ldg(eps_scores + row);
        if (nonana > 0.5f) bestM = fmaxf(bestM, e);

        const float row_cost = nonana * lc0 + (1.0f - nonana) * lc1;

        float loss = 0.0f;
        loss = fmaxf(loss, row_cost * (1.0f + maxU - bestM));   // -inf-safe
        const float dcost = (1.0f - nonana) * fnc;
        loss = fmaxf(loss, dcost * (1.0f + e - bestM));

        out[row] = loss;
    }
}

extern "C" void kernel_launch(void* const* d_in, const int* in_sizes, int n_in,
                              void* d_out, int out_size)
{
    const float* eps  = (const float*)d_in[0];
    const float* ana  = (const float*)d_in[1];
    const float* mask = (const float*)d_in[2];
    const float* lc   = (const float*)d_in[3];
    const float* fnc  = (const float*)d_in[4];
    float* out = (float*)d_out;

    mention_loss_kernel<<<NMENT / 2, BLOCK>>>(eps, ana, mask, lc, fnc, out);
}